// round 14
// baseline (speedup 1.0000x reference)
#include <cuda_runtime.h>

#define BB 2
#define TT 5
#define NNq 4096
#define CC 16
#define DD 128
#define NSrc 16384          // (T-1)*N
#define MM (BB*NNq)         // 8192
#define EPSV 1e-5f
#define RAD2 1.0f
#define NCH (NSrc/256)      // 64 super-chunks of 256 points
#define FASTCH 2            // fast-path chunks (512 points)

#define NBLK 148
#define NTHR 384
#define NWRP 12
#define GWARPS (NBLK*NWRP)

// ---------------- scratch (__device__ globals) ----------------
__device__ float4 g_xyzw[BB*NSrc];
__device__ float  g_hmax[(size_t)MM*DD];
__device__ float  g_hmin[(size_t)MM*DD];
__device__ float  g_y0[(size_t)MM*DD];
__device__ float  g_y1[(size_t)MM*DD];
__device__ float  g_y2[(size_t)MM*DD];
__device__ float  g_csum[DD];
__device__ float  g_csq[DD];
__device__ float  g_ysum[3*DD];
__device__ float  g_ysq[3*DD];
__device__ unsigned g_bar_cnt;
__device__ unsigned g_bar_gen;
// pending-query queue
__device__ int    g_pcount;
__device__ int    g_pend_gw[MM];
__device__ int    g_pend_cnt[MM];
__device__ int4   g_pend_idx[MM];
__device__ float4 g_pend_q[MM];

// ---------------- grid-wide barrier (all NBLK blocks resident) ----------------
__device__ __forceinline__ void grid_barrier() {
    __syncthreads();
    if (threadIdx.x == 0) {
        unsigned gen = *(volatile unsigned*)&g_bar_gen;
        __threadfence();
        if (atomicAdd(&g_bar_cnt, 1u) == NBLK - 1) {
            g_bar_cnt = 0;
            __threadfence();
            atomicExch(&g_bar_gen, gen + 1u);
        } else {
            while (*(volatile unsigned*)&g_bar_gen == gen) {}
            __threadfence();
        }
    }
    __syncthreads();
}

// packed f32x2 fma (sm_100+)
__device__ __forceinline__ unsigned long long ffma2(unsigned long long a,
                                                    unsigned long long b,
                                                    unsigned long long c) {
    unsigned long long d;
    asm("fma.rn.f32x2 %0, %1, %2, %3;" : "=l"(d) : "l"(a), "l"(b), "l"(c));
    return d;
}
__device__ __forceinline__ unsigned long long splat2(float w) {
    unsigned long long r;
    asm("mov.b64 %0, {%1, %1};" : "=l"(r) : "r"(__float_as_uint(w)));
    return r;
}
__device__ __forceinline__ void unpack2(unsigned long long v, float& lo, float& hi) {
    unsigned a, b;
    asm("mov.b64 {%0, %1}, %2;" : "=r"(a), "=r"(b) : "l"(v));
    lo = __uint_as_float(a); hi = __uint_as_float(b);
}

// gather + conv + store + stat accumulate for one query
__device__ __forceinline__ void do_conv(int gw, int i0, int i1, int i2, int i3,
        bool empty, const float* __restrict__ x,
        const float* __restrict__ conv_w, const float* __restrict__ conv_b,
        float* gg, int lane, float accS[4], float accQ[4]) {
    int b = gw >> 12;
    const float* feats = x + ((size_t)b*TT + 1)*NNq*CC;
    #pragma unroll
    for (int r = 0; r < 2; r++) {
        int v = lane + r*32;          // v = s*16 + c
        int s = v >> 4, c = v & 15;
        int id = (s == 0) ? i0 : (s == 1) ? i1 : (s == 2) ? i2 : i3;
        gg[v] = empty ? 0.0f : feats[(size_t)id*CC + c];
    }
    __syncwarp();
    float* hmaxr = g_hmax + (size_t)gw * DD;
    float* hminr = g_hmin + (size_t)gw * DD;
    #pragma unroll
    for (int j = 0; j < 4; j++) {
        int o = lane + j*32;
        float bo = conv_b[o];
        float a0 = bo, a1 = bo, a2 = bo, a3 = bo;
        const float* wr = conv_w + o*CC;
        #pragma unroll
        for (int c = 0; c < CC; c++) {
            float wv = wr[c];
            a0 = fmaf(wv, gg[0*16 + c], a0);
            a1 = fmaf(wv, gg[1*16 + c], a1);
            a2 = fmaf(wv, gg[2*16 + c], a2);
            a3 = fmaf(wv, gg[3*16 + c], a3);
        }
        float mx = fmaxf(fmaxf(a0, a1), fmaxf(a2, a3));
        float mn = fminf(fminf(a0, a1), fminf(a2, a3));
        hmaxr[o] = mx;
        hminr[o] = mn;
        accS[j] += a0 + a1 + a2 + a3;
        accQ[j] += a0*a0 + a1*a1 + a2*a2 + a3*a3;
    }
    __syncwarp();
}

// ---------------- smem layout ----------------
#define MTILE 64
#define SH_OFF 256
#define SH_PITCH 68
#define SW_OFF (SH_OFF + DD*SH_PITCH)
#define SW_PITCH 36
#define SMEM_FLOATS (SW_OFF + 3*DD*SW_PITCH)   // 22784 floats = 91136 B

__global__ void __launch_bounds__(NTHR, 1) k_fused(
        const float* __restrict__ x,
        const float* __restrict__ conv_w, const float* __restrict__ conv_b,
        const float* __restrict__ bng,    const float* __restrict__ bnb,
        const float* __restrict__ fc1w,   const float* __restrict__ fc1b,
        const float* __restrict__ fc2w,   const float* __restrict__ fc2b,
        const float* __restrict__ fc3w,   const float* __restrict__ fc3b,
        const float* __restrict__ cew,    const float* __restrict__ ceb,
        const float* __restrict__ lww,    const float* __restrict__ lwb,
        const float* __restrict__ thw,    const float* __restrict__ thb,
        float* __restrict__ out, float* __restrict__ feat_out) {
    extern __shared__ float sm[];
    int tid  = threadIdx.x;
    int wrp  = tid >> 5;
    int lane = tid & 31;
    int gwarp = blockIdx.x * NWRP + wrp;

    // ================= Phase 0: pack + zero accumulators =================
    {
        int idx0 = blockIdx.x * NTHR + tid;
        if (idx0 == 0)    g_pcount = 0;
        if (idx0 < DD)   { g_csum[idx0] = 0.f; g_csq[idx0] = 0.f; }
        if (idx0 < 3*DD) { g_ysum[idx0] = 0.f; g_ysq[idx0] = 0.f; }
        for (int i = idx0; i < BB*NSrc; i += NBLK*NTHR) {
            int b = i / NSrc, j = i % NSrc;
            int t = 1 + j / NNq, n = j % NNq;
            const float* p = x + (((size_t)b*TT + t)*NNq + n)*CC;
            float px = p[0], py = p[1], pz = p[2];
            g_xyzw[i] = make_float4(px, py, pz, px*px + py*py + pz*pz);
        }
    }
    grid_barrier();

    // ================= Phase 1a: fast path (512 pts) + conv =================
    {
        float* sg    = sm;                       // [12][64]
        float* swsum = sm + NWRP*64;
        float* swsq  = swsum + NWRP*DD;
        float accS[4] = {0.f,0.f,0.f,0.f};
        float accQ[4] = {0.f,0.f,0.f,0.f};
        float* gg = &sg[wrp*64];

        for (int gw = gwarp; gw < MM; gw += GWARPS) {
            int b = gw >> 12, q = gw & (NNq - 1);
            const float* qp = x + (((size_t)b*TT + 0)*NNq + q)*CC;
            float qx = qp[0], qy = qp[1], qz = qp[2];
            float qq = qx*qx + qy*qy + qz*qz;

            const float4* src = g_xyzw + (size_t)b*NSrc;
            int i0 = 0, i1 = 0, i2 = 0, i3 = 0, cnt = 0;

            for (int sc = 0; sc < FASTCH && cnt < 4; sc++) {
                float4 C[8];
                #pragma unroll
                for (int j = 0; j < 8; j++) C[j] = src[sc*256 + j*32 + lane];
                #pragma unroll
                for (int j = 0; j < 8; j++) {
                    float dot = fmaf(qx, C[j].x, fmaf(qy, C[j].y, qz*C[j].z));
                    float d2  = fmaf(-2.0f, dot, qq + C[j].w);
                    unsigned mask = __ballot_sync(0xffffffffu, d2 < RAD2);
                    while (mask && cnt < 4) {
                        int id = sc*256 + j*32 + (__ffs(mask) - 1);
                        if      (cnt == 0) i0 = id;
                        else if (cnt == 1) i1 = id;
                        else if (cnt == 2) i2 = id;
                        else               i3 = id;
                        cnt++;
                        mask &= mask - 1;
                    }
                }
            }
            if (cnt < 4) {
                if (lane == 0) {
                    int pos = atomicAdd(&g_pcount, 1);
                    g_pend_gw[pos]  = gw;
                    g_pend_cnt[pos] = cnt;
                    g_pend_idx[pos] = make_int4(i0, i1, i2, i3);
                    g_pend_q[pos]   = make_float4(qx, qy, qz, qq);
                }
                continue;
            }
            do_conv(gw, i0, i1, i2, i3, false, x, conv_w, conv_b, gg, lane, accS, accQ);
        }
        grid_barrier();

        // ============= Phase 1b: drain pending queue (1 warp / query) =============
        int pcount = *(volatile int*)&g_pcount;
        for (int pi = gwarp; pi < pcount; pi += GWARPS) {
            int gw   = g_pend_gw[pi];
            int cnt  = g_pend_cnt[pi];
            int4 ii  = g_pend_idx[pi];
            float4 qd = g_pend_q[pi];
            int i0 = ii.x, i1 = ii.y, i2 = ii.z, i3 = ii.w;
            float qx = qd.x, qy = qd.y, qz = qd.z, qq = qd.w;
            const float4* src = g_xyzw + (size_t)(gw >> 12)*NSrc;

            float4 P[8];
            #pragma unroll
            for (int j = 0; j < 8; j++) P[j] = src[FASTCH*256 + j*32 + lane];
            for (int sc = FASTCH; sc < NCH && cnt < 4; sc++) {
                float4 C[8];
                #pragma unroll
                for (int j = 0; j < 8; j++) C[j] = P[j];
                int nxt = (sc + 1 < NCH) ? sc + 1 : sc;
                #pragma unroll
                for (int j = 0; j < 8; j++) P[j] = src[nxt*256 + j*32 + lane];
                #pragma unroll
                for (int j = 0; j < 8; j++) {
                    float dot = fmaf(qx, C[j].x, fmaf(qy, C[j].y, qz*C[j].z));
                    float d2  = fmaf(-2.0f, dot, qq + C[j].w);
                    unsigned mask = __ballot_sync(0xffffffffu, d2 < RAD2);
                    while (mask && cnt < 4) {
                        int id = sc*256 + j*32 + (__ffs(mask) - 1);
                        if      (cnt == 0) i0 = id;
                        else if (cnt == 1) i1 = id;
                        else if (cnt == 2) i2 = id;
                        else               i3 = id;
                        cnt++;
                        mask &= mask - 1;
                    }
                }
            }
            bool empty = (cnt == 0);
            if (cnt < 2) i1 = i0;
            if (cnt < 3) i2 = i0;
            if (cnt < 4) i3 = i0;
            do_conv(gw, i0, i1, i2, i3, empty, x, conv_w, conv_b, gg, lane, accS, accQ);
        }

        // block-reduce stats -> global atomics
        #pragma unroll
        for (int j = 0; j < 4; j++) {
            swsum[wrp*DD + lane + j*32] = accS[j];
            swsq [wrp*DD + lane + j*32] = accQ[j];
        }
        __syncthreads();
        if (tid < DD) {
            float s = 0.f, qv = 0.f;
            #pragma unroll
            for (int u = 0; u < NWRP; u++) { s += swsum[u*DD + tid]; qv += swsq[u*DD + tid]; }
            atomicAdd(&g_csum[tid], s);
            atomicAdd(&g_csq[tid],  qv);
        }
    }
    grid_barrier();

    // ================= Phase 2: BN+maxpool + c-blocked GEMM + y-stats =================
    if (blockIdx.x < MM/MTILE) {
        float* sscale = sm;
        float* sshift = sm + DD;
        float* sh     = sm + SH_OFF;   // [o][m] pitch 68
        float* sw     = sm + SW_OFF;   // [k][c][oi] pitch 36
        int m0 = blockIdx.x * MTILE;

        if (tid < DD) {
            float inv = 1.0f / (float)(MM*4);
            float mean = g_csum[tid] * inv;
            float var  = g_csq[tid] * inv - mean*mean;
            float sc = bng[tid] * rsqrtf(var + EPSV);
            sscale[tid] = sc;
            sshift[tid] = bnb[tid] - mean * sc;
        }
        __syncthreads();

        for (int v = tid; v < MTILE*DD; v += NTHR) {
            int mi = v >> 7, o = v & 127;
            float hx = g_hmax[(size_t)(m0+mi)*DD + o];
            float hn = g_hmin[(size_t)(m0+mi)*DD + o];
            float sc = sscale[o], sf = sshift[o];
            float hv = fmaxf(fmaf(sc, hx, sf), fmaf(sc, hn, sf));
            sh[o*SH_PITCH + mi] = hv;
            feat_out[(size_t)(m0+mi)*DD + o] = hv;
        }

        int mh = tid & 3;
        int cg = (tid >> 2) & 31;
        int k  = tid >> 7;
        int c0 = cg * 4;
        const float* fbk = (k == 0) ? fc1b : (k == 1) ? fc2b : fc3b;
        unsigned long long acc[4][8];
        #pragma unroll
        for (int i = 0; i < 4; i++) {
            unsigned long long b2 = splat2(fbk[c0 + i]);
            #pragma unroll
            for (int j = 0; j < 8; j++) acc[i][j] = b2;
        }

        for (int oc = 0; oc < 4; oc++) {
            __syncthreads();
            for (int v = tid; v < 3*DD*32; v += NTHR) {
                int kk = v >> 12, rest = v & 4095;
                int cc = rest >> 5, oi = rest & 31;
                const float* Ws = (kk == 0) ? fc1w : (kk == 1) ? fc2w : fc3w;
                sw[(kk*DD + cc)*SW_PITCH + oi] = Ws[(size_t)cc*DD + oc*32 + oi];
            }
            __syncthreads();
            const float* swb = sw + (size_t)(k*DD + c0)*SW_PITCH;
            #pragma unroll
            for (int og = 0; og < 8; og++) {
                int oi0 = og * 4;
                float4 wv[4];
                #pragma unroll
                for (int i = 0; i < 4; i++)
                    wv[i] = *(const float4*)(swb + i*SW_PITCH + oi0);
                #pragma unroll
                for (int u = 0; u < 4; u++) {
                    int o = oc*32 + oi0 + u;
                    const ulonglong2* hp =
                        reinterpret_cast<const ulonglong2*>(sh + o*SH_PITCH + mh*16);
                    ulonglong2 hA = hp[0], hB = hp[1], hC = hp[2], hD = hp[3];
                    #pragma unroll
                    for (int i = 0; i < 4; i++) {
                        float wvu = (u == 0) ? wv[i].x : (u == 1) ? wv[i].y
                                  : (u == 2) ? wv[i].z : wv[i].w;
                        unsigned long long w2 = splat2(wvu);
                        acc[i][0] = ffma2(w2, hA.x, acc[i][0]);
                        acc[i][1] = ffma2(w2, hA.y, acc[i][1]);
                        acc[i][2] = ffma2(w2, hB.x, acc[i][2]);
                        acc[i][3] = ffma2(w2, hB.y, acc[i][3]);
                        acc[i][4] = ffma2(w2, hC.x, acc[i][4]);
                        acc[i][5] = ffma2(w2, hC.y, acc[i][5]);
                        acc[i][6] = ffma2(w2, hD.x, acc[i][6]);
                        acc[i][7] = ffma2(w2, hD.y, acc[i][7]);
                    }
                }
            }
        }

        float* yk = (k == 0) ? g_y0 : (k == 1) ? g_y1 : g_y2;
        float ss[4] = {0.f,0.f,0.f,0.f};
        float sq[4] = {0.f,0.f,0.f,0.f};
        #pragma unroll
        for (int j = 0; j < 8; j++) {
            float lo[4], hi[4];
            #pragma unroll
            for (int i = 0; i < 4; i++) {
                unpack2(acc[i][j], lo[i], hi[i]);
                ss[i] += lo[i] + hi[i];
                sq[i] += lo[i]*lo[i] + hi[i]*hi[i];
            }
            int mrow = m0 + mh*16 + 2*j;
            *(float4*)(yk + (size_t)mrow*DD + c0)     = make_float4(lo[0],lo[1],lo[2],lo[3]);
            *(float4*)(yk + (size_t)(mrow+1)*DD + c0) = make_float4(hi[0],hi[1],hi[2],hi[3]);
        }
        #pragma unroll
        for (int i = 0; i < 4; i++) {
            ss[i] += __shfl_xor_sync(0xffffffffu, ss[i], 1);
            ss[i] += __shfl_xor_sync(0xffffffffu, ss[i], 2);
            sq[i] += __shfl_xor_sync(0xffffffffu, sq[i], 1);
            sq[i] += __shfl_xor_sync(0xffffffffu, sq[i], 2);
        }
        if (mh == 0) {
            #pragma unroll
            for (int i = 0; i < 4; i++) {
                atomicAdd(&g_ysum[k*DD + c0 + i], ss[i]);
                atomicAdd(&g_ysq [k*DD + c0 + i], sq[i]);
            }
        }
    }
    grid_barrier();

    // ================= Phase 3: heads =================
    {
        float* ysc = sm;
        float* ysh = sm + 3*DD;
        for (int v = tid; v < 3*DD; v += NTHR) {
            int c = v & 127;
            float inv = 1.0f / (float)MM;
            float mean = g_ysum[v] * inv;
            float var  = g_ysq[v] * inv - mean*mean;
            float sc = bng[c] * rsqrtf(var + EPSV);
            ysc[v] = sc;
            ysh[v] = bnb[c] - mean * sc;
        }
        __syncthreads();

        int o = lane * 4;
        float4 wce0 = *(const float4*)(cew + 0*DD + o);
        float4 wce1 = *(const float4*)(cew + 1*DD + o);
        float4 wce2 = *(const float4*)(cew + 2*DD + o);
        float4 wlw0 = *(const float4*)(lww + 0*DD + o);
        float4 wlw1 = *(const float4*)(lww + 1*DD + o);
        float4 wlw2 = *(const float4*)(lww + 2*DD + o);
        float4 wth  = *(const float4*)(thw + o);

        for (int job = gwarp; job < MM/4; job += GWARPS) {
            int gwb = job * 4;
            float4 y0[4], y1[4], y2[4];
            #pragma unroll
            for (int km = 0; km < 4; km++) {
                y0[km] = *(const float4*)(g_y0 + (size_t)(gwb+km)*DD + o);
                y1[km] = *(const float4*)(g_y1 + (size_t)(gwb+km)*DD + o);
                y2[km] = *(const float4*)(g_y2 + (size_t)(gwb+km)*DD + o);
            }
            float r[7][4];
            #pragma unroll
            for (int km = 0; km < 4; km++) {
                {
                    float x0 = fmaxf(0.f, fmaf(ysc[0*DD+o+0], y0[km].x, ysh[0*DD+o+0]));
                    float x1 = fmaxf(0.f, fmaf(ysc[0*DD+o+1], y0[km].y, ysh[0*DD+o+1]));
                    float x2 = fmaxf(0.f, fmaf(ysc[0*DD+o+2], y0[km].z, ysh[0*DD+o+2]));
                    float x3 = fmaxf(0.f, fmaf(ysc[0*DD+o+3], y0[km].w, ysh[0*DD+o+3]));
                    r[0][km] = x0*wce0.x + x1*wce0.y + x2*wce0.z + x3*wce0.w;
                    r[1][km] = x0*wce1.x + x1*wce1.y + x2*wce1.z + x3*wce1.w;
                    r[2][km] = x0*wce2.x + x1*wce2.y + x2*wce2.z + x3*wce2.w;
                }
                {
                    float x0 = fmaxf(0.f, fmaf(ysc[1*DD+o+0], y1[km].x, ysh[1*DD+o+0]));
                    float x1 = fmaxf(0.f, fmaf(ysc[1*DD+o+1], y1[km].y, ysh[1*DD+o+1]));
                    float x2 = fmaxf(0.f, fmaf(ysc[1*DD+o+2], y1[km].z, ysh[1*DD+o+2]));
                    float x3 = fmaxf(0.f, fmaf(ysc[1*DD+o+3], y1[km].w, ysh[1*DD+o+3]));
                    r[3][km] = x0*wlw0.x + x1*wlw0.y + x2*wlw0.z + x3*wlw0.w;
                    r[4][km] = x0*wlw1.x + x1*wlw1.y + x2*wlw1.z + x3*wlw1.w;
                    r[5][km] = x0*wlw2.x + x1*wlw2.y + x2*wlw2.z + x3*wlw2.w;
                }
                {
                    float x0 = fmaxf(0.f, fmaf(ysc[2*DD+o+0], y2[km].x, ysh[2*DD+o+0]));
                    float x1 = fmaxf(0.f, fmaf(ysc[2*DD+o+1], y2[km].y, ysh[2*DD+o+1]));
                    float x2 = fmaxf(0.f, fmaf(ysc[2*DD+o+2], y2[km].z, ysh[2*DD+o+2]));
                    float x3 = fmaxf(0.f, fmaf(ysc[2*DD+o+3], y2[km].w, ysh[2*DD+o+3]));
                    r[6][km] = x0*wth.x + x1*wth.y + x2*wth.z + x3*wth.w;
                }
            }
            #pragma unroll
            for (int h = 0; h < 7; h++)
                #pragma unroll
                for (int km = 0; km < 4; km++)
                    #pragma unroll
                    for (int off = 16; off; off >>= 1)
                        r[h][km] += __shfl_xor_sync(0xffffffffu, r[h][km], off);

            if (lane == 0) {
                #pragma unroll
                for (int km = 0; km < 4; km++) {
                    float* op = out + (size_t)(gwb + km)*7;
                    op[0] = r[0][km] + ceb[0];
                    op[1] = r[1][km] + ceb[1];
                    op[2] = r[2][km] + ceb[2];
                    op[3] = r[3][km] + lwb[0];
                    op[4] = r[4][km] + lwb[1];
                    op[5] = r[5][km] + lwb[2];
                    op[6] = r[6][km] + thb[0];
                }
            }
        }
    }
}

// ---------------- launch ----------------
extern "C" void kernel_launch(void* const* d_in, const int* in_sizes, int n_in,
                              void* d_out, int out_size) {
    const float* x        = (const float*)d_in[0];
    const float* conv1_w  = (const float*)d_in[1];
    const float* conv1_b  = (const float*)d_in[2];
    const float* bn_g     = (const float*)d_in[3];
    const float* bn_b     = (const float*)d_in[4];
    const float* fc1_w    = (const float*)d_in[5];
    const float* fc1_b    = (const float*)d_in[6];
    const float* fc_ce_w  = (const float*)d_in[7];
    const float* fc_ce_b  = (const float*)d_in[8];
    const float* fc2_w    = (const float*)d_in[9];
    const float* fc2_b    = (const float*)d_in[10];
    const float* fc_lwh_w = (const float*)d_in[11];
    const float* fc_lwh_b = (const float*)d_in[12];
    const float* fc3_w    = (const float*)d_in[13];
    const float* fc3_b    = (const float*)d_in[14];
    const float* fc_th_w  = (const float*)d_in[15];
    const float* fc_th_b  = (const float*)d_in[16];

    float* out  = (float*)d_out;             // (B,N,7) flattened
    float* feat = out + (size_t)MM * 7;      // (B,N,128) flattened after it

    static bool attr_set = false;
    if (!attr_set) {
        cudaFuncSetAttribute(k_fused, cudaFuncAttributeMaxDynamicSharedMemorySize,
                             SMEM_FLOATS * (int)sizeof(float));
        attr_set = true;
    }

    k_fused<<<NBLK, NTHR, SMEM_FLOATS * sizeof(float)>>>(
        x, conv1_w, conv1_b, bn_g, bn_b,
        fc1_w, fc1_b, fc2_w, fc2_b, fc3_w, fc3_b,
        fc_ce_w, fc_ce_b, fc_lwh_w, fc_lwh_b, fc_th_w, fc_th_b,
        out, feat);
}

// round 17
// speedup vs baseline: 1.4323x; 1.4323x over previous
#include <cuda_runtime.h>

#define BB 2
#define TT 5
#define NNq 4096
#define CC 16
#define DD 128
#define NSrc 16384          // (T-1)*N
#define MM (BB*NNq)         // 8192
#define EPSV 1e-5f
#define RAD2 1.0f
#define NCH (NSrc/256)

// ---------------- scratch (__device__ globals) ----------------
__device__ float4 g_xyzw[BB*NSrc];
__device__ float  g_hmax[(size_t)MM*DD];
__device__ float  g_hmin[(size_t)MM*DD];
__device__ float  g_y0[(size_t)MM*DD];
__device__ float  g_y1[(size_t)MM*DD];
__device__ float  g_y2[(size_t)MM*DD];
__device__ float  g_csum[DD];
__device__ float  g_csq[DD];
__device__ float  g_ysum[3*DD];
__device__ float  g_ysq[3*DD];

// packed f32x2 fma (sm_100+)
__device__ __forceinline__ unsigned long long ffma2(unsigned long long a,
                                                    unsigned long long b,
                                                    unsigned long long c) {
    unsigned long long d;
    asm("fma.rn.f32x2 %0, %1, %2, %3;" : "=l"(d) : "l"(a), "l"(b), "l"(c));
    return d;
}
__device__ __forceinline__ unsigned long long splat2(float w) {
    unsigned long long r;
    asm("mov.b64 %0, {%1, %1};" : "=l"(r) : "r"(__float_as_uint(w)));
    return r;
}
__device__ __forceinline__ void unpack2(unsigned long long v, float& lo, float& hi) {
    unsigned a, b;
    asm("mov.b64 {%0, %1}, %2;" : "=r"(a), "=r"(b) : "l"(v));
    lo = __uint_as_float(a); hi = __uint_as_float(b);
}

// ---------------- K1: pack source xyz + sumsq, zero accumulators ----------------
__global__ void k_pack(const float* __restrict__ x) {
    int i = blockIdx.x * blockDim.x + threadIdx.x;
    if (i < DD)   { g_csum[i] = 0.f; g_csq[i] = 0.f; }
    if (i < 3*DD) { g_ysum[i] = 0.f; g_ysq[i] = 0.f; }
    if (i >= BB*NSrc) return;
    int b = i / NSrc, j = i % NSrc;
    int t = 1 + j / NNq, n = j % NNq;
    const float* p = x + (((size_t)b*TT + t)*NNq + n)*CC;
    float px = p[0], py = p[1], pz = p[2];
    g_xyzw[i] = make_float4(px, py, pz, px*px + py*py + pz*pz);
}

// ---------------- K2: ball query + conv (smem-staged weights) + BN stats ----------
__global__ void __launch_bounds__(256, 2) k_ballconv(const float* __restrict__ x,
                           const float* __restrict__ w,
                           const float* __restrict__ bias) {
    __shared__ float swt[CC*DD];       // transposed weights: swt[c*128 + o]
    __shared__ float sb[DD];           // bias
    __shared__ float sg[8][64];        // per-warp grouped feats [s][c]
    __shared__ float swsum[8][DD];     // per-warp exclusive stat slots
    __shared__ float swsq[8][DD];
    int tid  = threadIdx.x;
    int wrp  = tid >> 5;
    int gw   = (blockIdx.x * blockDim.x + tid) >> 5;
    int lane = tid & 31;

    // stage weights transposed (one-time)
    for (int v = tid; v < CC*DD; v += 256) {
        int o = v >> 4, c = v & 15;     // read w row-major coalesced
        swt[c*DD + o] = w[v];
    }
    if (tid < DD) sb[tid] = bias[tid];
    __syncthreads();

    int b = gw >> 12, q = gw & (NNq - 1);

    const float* qp = x + (((size_t)b*TT + 0)*NNq + q)*CC;
    float qx = qp[0], qy = qp[1], qz = qp[2];
    float qq = qx*qx + qy*qy + qz*qz;

    const float4* src = g_xyzw + (size_t)b*NSrc;
    int i0 = 0, i1 = 0, i2 = 0, i3 = 0, cnt = 0;

    // pipelined coalesced scan: 256 pts per super-chunk, prefetch next
    float4 P[8];
    #pragma unroll
    for (int j = 0; j < 8; j++) P[j] = src[j*32 + lane];
    for (int sc = 0; sc < NCH && cnt < 4; sc++) {
        float4 C[8];
        #pragma unroll
        for (int j = 0; j < 8; j++) C[j] = P[j];
        int nxt = (sc + 1 < NCH) ? sc + 1 : sc;
        #pragma unroll
        for (int j = 0; j < 8; j++) P[j] = src[nxt*256 + j*32 + lane];
        #pragma unroll
        for (int j = 0; j < 8; j++) {
            float dot = fmaf(qx, C[j].x, fmaf(qy, C[j].y, qz*C[j].z));
            float d2  = fmaf(-2.0f, dot, qq + C[j].w);
            unsigned mask = __ballot_sync(0xffffffffu, d2 < RAD2);
            while (mask && cnt < 4) {
                int id = sc*256 + j*32 + (__ffs(mask) - 1);
                if      (cnt == 0) i0 = id;
                else if (cnt == 1) i1 = id;
                else if (cnt == 2) i2 = id;
                else               i3 = id;
                cnt++;
                mask &= mask - 1;
            }
        }
    }
    bool empty = (cnt == 0);
    if (cnt < 2) i1 = i0;
    if (cnt < 3) i2 = i0;
    if (cnt < 4) i3 = i0;

    // gather grouped feats into shared (g[s][c])
    float* gg = &sg[wrp][0];
    const float* feats = x + ((size_t)b*TT + 1)*NNq*CC;
    #pragma unroll
    for (int r = 0; r < 2; r++) {
        int v = lane + r*32;          // v = s*16 + c
        int s = v >> 4, c = v & 15;
        int id = (s == 0) ? i0 : (s == 1) ? i1 : (s == 2) ? i2 : i3;
        gg[v] = empty ? 0.0f : feats[(size_t)id*CC + c];
    }
    __syncwarp();

    // conv: weights from smem (conflict-free LDS), zero global traffic
    float* hmaxr = g_hmax + (size_t)gw * DD;
    float* hminr = g_hmin + (size_t)gw * DD;
    #pragma unroll
    for (int j = 0; j < 4; j++) {
        int o = lane + j*32;
        float bo = sb[o];
        float a0 = bo, a1 = bo, a2 = bo, a3 = bo;
        #pragma unroll
        for (int c = 0; c < CC; c++) {
            float wv = swt[c*DD + o];
            a0 = fmaf(wv, gg[0*16 + c], a0);
            a1 = fmaf(wv, gg[1*16 + c], a1);
            a2 = fmaf(wv, gg[2*16 + c], a2);
            a3 = fmaf(wv, gg[3*16 + c], a3);
        }
        float mx = fmaxf(fmaxf(a0, a1), fmaxf(a2, a3));
        float mn = fminf(fminf(a0, a1), fminf(a2, a3));
        hmaxr[o] = mx;
        hminr[o] = mn;
        swsum[wrp][o] = a0 + a1 + a2 + a3;
        swsq[wrp][o]  = a0*a0 + a1*a1 + a2*a2 + a3*a3;
    }
    __syncthreads();
    if (tid < DD) {
        float s = 0.f, qv = 0.f;
        #pragma unroll
        for (int u = 0; u < 8; u++) { s += swsum[u][tid]; qv += swsq[u][tid]; }
        atomicAdd(&g_csum[tid], s);
        atomicAdd(&g_csq[tid],  qv);
    }
}

// ---------------- K3: scale + BN+maxpool + c-blocked fused GEMM + y-stats ---------
#define MTILE 64
#define SH_OFF 256
#define SH_PITCH 68
#define SW_OFF (SH_OFF + DD*SH_PITCH)
#define SW_PITCH 36
#define SMEM_FLOATS (SW_OFF + 3*DD*SW_PITCH)

__global__ void __launch_bounds__(384) k_gemm(
        const float* __restrict__ fc1w, const float* __restrict__ fc1b,
        const float* __restrict__ fc2w, const float* __restrict__ fc2b,
        const float* __restrict__ fc3w, const float* __restrict__ fc3b,
        const float* __restrict__ bng,  const float* __restrict__ bnb,
        float* __restrict__ feat_out) {
    extern __shared__ float sm[];
    float* sscale = sm;
    float* sshift = sm + DD;
    float* sh     = sm + SH_OFF;   // [o][m] pitch 68
    float* sw     = sm + SW_OFF;   // [k][c][oi] pitch 36
    int tid = threadIdx.x;
    int m0 = blockIdx.x * MTILE;

    if (tid < DD) {
        float inv = 1.0f / (float)(MM*4);
        float mean = g_csum[tid] * inv;
        float var  = g_csq[tid] * inv - mean*mean;
        float sc = bng[tid] * rsqrtf(var + EPSV);
        sscale[tid] = sc;
        sshift[tid] = bnb[tid] - mean * sc;
    }
    __syncthreads();

    for (int v = tid; v < MTILE*DD; v += 384) {
        int mi = v >> 7, o = v & 127;
        float hx = g_hmax[(size_t)(m0+mi)*DD + o];
        float hn = g_hmin[(size_t)(m0+mi)*DD + o];
        float sc = sscale[o], sf = sshift[o];
        float hv = fmaxf(fmaf(sc, hx, sf), fmaf(sc, hn, sf));
        sh[o*SH_PITCH + mi] = hv;
        feat_out[(size_t)(m0+mi)*DD + o] = hv;
    }

    // thread = (k, cg, mh): 4 channels c0..c0+3, 16 m rows mh*16..+16
    int mh = tid & 3;
    int cg = (tid >> 2) & 31;
    int k  = tid >> 7;
    int c0 = cg * 4;
    const float* fbk = (k == 0) ? fc1b : (k == 1) ? fc2b : fc3b;
    unsigned long long acc[4][8];
    #pragma unroll
    for (int i = 0; i < 4; i++) {
        unsigned long long b2 = splat2(fbk[c0 + i]);
        #pragma unroll
        for (int j = 0; j < 8; j++) acc[i][j] = b2;
    }

    for (int oc = 0; oc < 4; oc++) {
        __syncthreads();
        for (int v = tid; v < 3*DD*32; v += 384) {
            int kk = v >> 12, rest = v & 4095;
            int cc = rest >> 5, oi = rest & 31;
            const float* Ws = (kk == 0) ? fc1w : (kk == 1) ? fc2w : fc3w;
            sw[(kk*DD + cc)*SW_PITCH + oi] = Ws[(size_t)cc*DD + oc*32 + oi];
        }
        __syncthreads();
        const float* swb = sw + (size_t)(k*DD + c0)*SW_PITCH;
        #pragma unroll
        for (int og = 0; og < 8; og++) {
            int oi0 = og * 4;
            float4 wv[4];
            #pragma unroll
            for (int i = 0; i < 4; i++)
                wv[i] = *(const float4*)(swb + i*SW_PITCH + oi0);
            #pragma unroll
            for (int u = 0; u < 4; u++) {
                int o = oc*32 + oi0 + u;
                const ulonglong2* hp =
                    reinterpret_cast<const ulonglong2*>(sh + o*SH_PITCH + mh*16);
                ulonglong2 hA = hp[0], hB = hp[1], hC = hp[2], hD = hp[3];
                #pragma unroll
                for (int i = 0; i < 4; i++) {
                    float wvu = (u == 0) ? wv[i].x : (u == 1) ? wv[i].y
                              : (u == 2) ? wv[i].z : wv[i].w;
                    unsigned long long w2 = splat2(wvu);
                    acc[i][0] = ffma2(w2, hA.x, acc[i][0]);
                    acc[i][1] = ffma2(w2, hA.y, acc[i][1]);
                    acc[i][2] = ffma2(w2, hB.x, acc[i][2]);
                    acc[i][3] = ffma2(w2, hB.y, acc[i][3]);
                    acc[i][4] = ffma2(w2, hC.x, acc[i][4]);
                    acc[i][5] = ffma2(w2, hC.y, acc[i][5]);
                    acc[i][6] = ffma2(w2, hD.x, acc[i][6]);
                    acc[i][7] = ffma2(w2, hD.y, acc[i][7]);
                }
            }
        }
    }

    float* yk = (k == 0) ? g_y0 : (k == 1) ? g_y1 : g_y2;
    float ss[4] = {0.f,0.f,0.f,0.f};
    float sq[4] = {0.f,0.f,0.f,0.f};
    #pragma unroll
    for (int j = 0; j < 8; j++) {
        float lo[4], hi[4];
        #pragma unroll
        for (int i = 0; i < 4; i++) {
            unpack2(acc[i][j], lo[i], hi[i]);
            ss[i] += lo[i] + hi[i];
            sq[i] += lo[i]*lo[i] + hi[i]*hi[i];
        }
        int mrow = m0 + mh*16 + 2*j;
        *(float4*)(yk + (size_t)mrow*DD + c0)     = make_float4(lo[0],lo[1],lo[2],lo[3]);
        *(float4*)(yk + (size_t)(mrow+1)*DD + c0) = make_float4(hi[0],hi[1],hi[2],hi[3]);
    }
    #pragma unroll
    for (int i = 0; i < 4; i++) {
        ss[i] += __shfl_xor_sync(0xffffffffu, ss[i], 1);
        ss[i] += __shfl_xor_sync(0xffffffffu, ss[i], 2);
        sq[i] += __shfl_xor_sync(0xffffffffu, sq[i], 1);
        sq[i] += __shfl_xor_sync(0xffffffffu, sq[i], 2);
    }
    if (mh == 0) {
        #pragma unroll
        for (int i = 0; i < 4; i++) {
            atomicAdd(&g_ysum[k*DD + c0 + i], ss[i]);
            atomicAdd(&g_ysq [k*DD + c0 + i], sq[i]);
        }
    }
}

// ---------------- K4: y-scale + relu(BN(y)) -> 7 head outputs (4 m per warp) --------
__global__ void __launch_bounds__(256) k_out(
                      const float* __restrict__ cew, const float* __restrict__ ceb,
                      const float* __restrict__ lww, const float* __restrict__ lwb,
                      const float* __restrict__ thw, const float* __restrict__ thb,
                      const float* __restrict__ bng, const float* __restrict__ bnb,
                      float* __restrict__ out) {
    __shared__ float ysc[3*DD], ysh[3*DD];
    int tid = threadIdx.x;
    for (int v = tid; v < 3*DD; v += 256) {
        int c = v & 127;
        float inv = 1.0f / (float)MM;
        float mean = g_ysum[v] * inv;
        float var  = g_ysq[v] * inv - mean*mean;
        float sc = bng[c] * rsqrtf(var + EPSV);
        ysc[v] = sc;
        ysh[v] = bnb[c] - mean * sc;
    }
    __syncthreads();

    int warp = (blockIdx.x * blockDim.x + tid) >> 5;
    int lane = tid & 31;
    int gwb  = warp * 4;
    int o = lane * 4;

    float4 y0[4], y1[4], y2[4];
    #pragma unroll
    for (int km = 0; km < 4; km++) {
        y0[km] = *(const float4*)(g_y0 + (size_t)(gwb+km)*DD + o);
        y1[km] = *(const float4*)(g_y1 + (size_t)(gwb+km)*DD + o);
        y2[km] = *(const float4*)(g_y2 + (size_t)(gwb+km)*DD + o);
    }
    float4 wce0 = *(const float4*)(cew + 0*DD + o);
    float4 wce1 = *(const float4*)(cew + 1*DD + o);
    float4 wce2 = *(const float4*)(cew + 2*DD + o);
    float4 wlw0 = *(const float4*)(lww + 0*DD + o);
    float4 wlw1 = *(const float4*)(lww + 1*DD + o);
    float4 wlw2 = *(const float4*)(lww + 2*DD + o);
    float4 wth  = *(const float4*)(thw + o);

    float r[7][4];
    #pragma unroll
    for (int km = 0; km < 4; km++) {
        {
            float x0 = fmaxf(0.f, fmaf(ysc[0*DD+o+0], y0[km].x, ysh[0*DD+o+0]));
            float x1 = fmaxf(0.f, fmaf(ysc[0*DD+o+1], y0[km].y, ysh[0*DD+o+1]));
            float x2 = fmaxf(0.f, fmaf(ysc[0*DD+o+2], y0[km].z, ysh[0*DD+o+2]));
            float x3 = fmaxf(0.f, fmaf(ysc[0*DD+o+3], y0[km].w, ysh[0*DD+o+3]));
            r[0][km] = x0*wce0.x + x1*wce0.y + x2*wce0.z + x3*wce0.w;
            r[1][km] = x0*wce1.x + x1*wce1.y + x2*wce1.z + x3*wce1.w;
            r[2][km] = x0*wce2.x + x1*wce2.y + x2*wce2.z + x3*wce2.w;
        }
        {
            float x0 = fmaxf(0.f, fmaf(ysc[1*DD+o+0], y1[km].x, ysh[1*DD+o+0]));
            float x1 = fmaxf(0.f, fmaf(ysc[1*DD+o+1], y1[km].y, ysh[1*DD+o+1]));
            float x2 = fmaxf(0.f, fmaf(ysc[1*DD+o+2], y1[km].z, ysh[1*DD+o+2]));
            float x3 = fmaxf(0.f, fmaf(ysc[1*DD+o+3], y1[km].w, ysh[1*DD+o+3]));
            r[3][km] = x0*wlw0.x + x1*wlw0.y + x2*wlw0.z + x3*wlw0.w;
            r[4][km] = x0*wlw1.x + x1*wlw1.y + x2*wlw1.z + x3*wlw1.w;
            r[5][km] = x0*wlw2.x + x1*wlw2.y + x2*wlw2.z + x3*wlw2.w;
        }
        {
            float x0 = fmaxf(0.f, fmaf(ysc[2*DD+o+0], y2[km].x, ysh[2*DD+o+0]));
            float x1 = fmaxf(0.f, fmaf(ysc[2*DD+o+1], y2[km].y, ysh[2*DD+o+1]));
            float x2 = fmaxf(0.f, fmaf(ysc[2*DD+o+2], y2[km].z, ysh[2*DD+o+2]));
            float x3 = fmaxf(0.f, fmaf(ysc[2*DD+o+3], y2[km].w, ysh[2*DD+o+3]));
            r[6][km] = x0*wth.x + x1*wth.y + x2*wth.z + x3*wth.w;
        }
    }
    #pragma unroll
    for (int h = 0; h < 7; h++)
        #pragma unroll
        for (int km = 0; km < 4; km++)
            #pragma unroll
            for (int off = 16; off; off >>= 1)
                r[h][km] += __shfl_xor_sync(0xffffffffu, r[h][km], off);

    if (lane == 0) {
        #pragma unroll
        for (int km = 0; km < 4; km++) {
            float* op = out + (size_t)(gwb + km)*7;
            op[0] = r[0][km] + ceb[0];
            op[1] = r[1][km] + ceb[1];
            op[2] = r[2][km] + ceb[2];
            op[3] = r[3][km] + lwb[0];
            op[4] = r[4][km] + lwb[1];
            op[5] = r[5][km] + lwb[2];
            op[6] = r[6][km] + thb[0];
        }
    }
}

// ---------------- launch ----------------
extern "C" void kernel_launch(void* const* d_in, const int* in_sizes, int n_in,
                              void* d_out, int out_size) {
    const float* x        = (const float*)d_in[0];
    const float* conv1_w  = (const float*)d_in[1];
    const float* conv1_b  = (const float*)d_in[2];
    const float* bn_g     = (const float*)d_in[3];
    const float* bn_b     = (const float*)d_in[4];
    const float* fc1_w    = (const float*)d_in[5];
    const float* fc1_b    = (const float*)d_in[6];
    const float* fc_ce_w  = (const float*)d_in[7];
    const float* fc_ce_b  = (const float*)d_in[8];
    const float* fc2_w    = (const float*)d_in[9];
    const float* fc2_b    = (const float*)d_in[10];
    const float* fc_lwh_w = (const float*)d_in[11];
    const float* fc_lwh_b = (const float*)d_in[12];
    const float* fc3_w    = (const float*)d_in[13];
    const float* fc3_b    = (const float*)d_in[14];
    const float* fc_th_w  = (const float*)d_in[15];
    const float* fc_th_b  = (const float*)d_in[16];

    float* out  = (float*)d_out;             // (B,N,7) flattened
    float* feat = out + (size_t)MM * 7;      // (B,N,128) flattened after it

    static bool attr_set = false;
    if (!attr_set) {
        cudaFuncSetAttribute(k_gemm, cudaFuncAttributeMaxDynamicSharedMemorySize,
                             SMEM_FLOATS * (int)sizeof(float));
        attr_set = true;
    }

    k_pack<<<(BB*NSrc + 255)/256, 256>>>(x);
    k_ballconv<<<MM/8, 256>>>(x, conv1_w, conv1_b);
    k_gemm<<<MM/MTILE, 384, SMEM_FLOATS * sizeof(float)>>>(
        fc1_w, fc1_b, fc2_w, fc2_b, fc3_w, fc3_b, bn_g, bn_b, feat);
    k_out<<<MM/32, 256>>>(fc_ce_w, fc_ce_b, fc_lwh_w, fc_lwh_b, fc_th_w, fc_th_b,
                          bn_g, bn_b, out);
}